// round 16
// baseline (speedup 1.0000x reference)
#include <cuda_runtime.h>
#include <cuda_bf16.h>
#include <math.h>
#include <stdint.h>

// Problem constants
#define Bb    4
#define Tt    2048
#define Cc    1024
#define Hh    16
#define HDd   64
#define MROWS (Bb*Tt)      // 8192
#define THREEC (3*Cc)      // 3072
#define BH    (Bb*Hh)      // 64

// Scratch: block-formatted operands. 16KB block = 128 rows x 128B;
// chunks 0-3 = hi plane (k 0..31), chunks 4-7 = lo plane.
__device__ __nv_bfloat16 g_Ablk[(size_t)MROWS * Cc * 2];    // 32MB
__device__ __nv_bfloat16 g_Bblk[(size_t)THREEC * Cc * 2];   // 12MB (Wqkv)
__device__ __nv_bfloat16 g_Wp[(size_t)Cc * Cc * 2];         // 4MB  (Wproj)
__device__ __nv_bfloat16 g_qh[(size_t)BH * Tt * HDd];
__device__ __nv_bfloat16 g_ql[(size_t)BH * Tt * HDd];
__device__ __nv_bfloat16 g_kh[(size_t)BH * Tt * HDd];
__device__ __nv_bfloat16 g_kl[(size_t)BH * Tt * HDd];
__device__ __nv_bfloat16 g_vh[(size_t)BH * Tt * HDd];
__device__ __nv_bfloat16 g_vl[(size_t)BH * Tt * HDd];

__device__ __forceinline__ uint32_t smem_u32(const void* p) {
    return (uint32_t)__cvta_generic_to_shared(p);
}
__device__ __forceinline__ void mbar_init(uint32_t a, uint32_t cnt) {
    asm volatile("mbarrier.init.shared.b64 [%0], %1;" :: "r"(a), "r"(cnt) : "memory");
}
__device__ __forceinline__ void mbar_expect(uint32_t a, uint32_t tx) {
    asm volatile("mbarrier.arrive.expect_tx.shared.b64 _, [%0], %1;"
                 :: "r"(a), "r"(tx) : "memory");
}
__device__ __forceinline__ void mbar_arrive(uint32_t a) {
    asm volatile("mbarrier.arrive.shared.b64 _, [%0];" :: "r"(a) : "memory");
}
__device__ __forceinline__ void mbar_wait(uint32_t a, uint32_t ph) {
    asm volatile(
        "{\n\t.reg .pred P;\n\t"
        "WL%=:\n\t"
        "mbarrier.try_wait.parity.shared::cta.b64 P, [%0], %1, 0x989680;\n\t"
        "@!P bra WL%=;\n\t}"
        :: "r"(a), "r"(ph) : "memory");
}
__device__ __forceinline__ void bulk_g2s(uint32_t dst, const void* src,
                                         uint32_t bytes, uint32_t mbar) {
    asm volatile(
        "cp.async.bulk.shared::cluster.global.mbarrier::complete_tx::bytes "
        "[%0], [%1], %2, [%3];"
        :: "r"(dst), "l"(src), "r"(bytes), "r"(mbar) : "memory");
}

#define LDSM4(r0, r1, r2, r3, a)                                              \
    asm volatile("ldmatrix.sync.aligned.m8n8.x4.shared.b16 {%0,%1,%2,%3}, [%4];" \
                 : "=r"(r0), "=r"(r1), "=r"(r2), "=r"(r3) : "r"(a))
#define LDSM4T(r0, r1, r2, r3, a)                                             \
    asm volatile("ldmatrix.sync.aligned.m8n8.x4.trans.shared.b16 {%0,%1,%2,%3}, [%4];" \
                 : "=r"(r0), "=r"(r1), "=r"(r2), "=r"(r3) : "r"(a))
#define MMA_BF16(c, a, b0, b1)                                                \
    asm volatile(                                                             \
        "mma.sync.aligned.m16n8k16.row.col.f32.bf16.bf16.f32 "                \
        "{%0,%1,%2,%3},{%4,%5,%6,%7},{%8,%9},{%0,%1,%2,%3};"                  \
        : "+f"((c)[0]), "+f"((c)[1]), "+f"((c)[2]), "+f"((c)[3])              \
        : "r"((a)[0]), "r"((a)[1]), "r"((a)[2]), "r"((a)[3]),                 \
          "r"(b0), "r"(b1))

__device__ __forceinline__ uint32_t swz(int row, int chunk) {
    return (uint32_t)(row * 128 + (((chunk) ^ (row & 7)) << 4));
}
__device__ __forceinline__ void split2(float a, float b, uint32_t& hi, uint32_t& lo) {
    __nv_bfloat16 ha = __float2bfloat16_rn(a);
    __nv_bfloat16 hb = __float2bfloat16_rn(b);
    __nv_bfloat16 la = __float2bfloat16_rn(a - __bfloat162float(ha));
    __nv_bfloat16 lb = __float2bfloat16_rn(b - __bfloat162float(hb));
    hi = ((uint32_t)__bfloat16_as_ushort(hb) << 16) | __bfloat16_as_ushort(ha);
    lo = ((uint32_t)__bfloat16_as_ushort(lb) << 16) | __bfloat16_as_ushort(la);
}

// ---------------------------------------------------------------------------
// Fused convert (vectorized): 4 floats/thread, one uint64 store per plane.
// ---------------------------------------------------------------------------
#define NXQ  (MROWS * 256)
#define NQQ  (THREEC * 256)
#define NWQ  (Cc * 256)

__global__ __launch_bounds__(256)
void convert_all(const float* __restrict__ X, const float* __restrict__ Wq,
                 const float* __restrict__ Wpj,
                 __nv_bfloat16* __restrict__ dstA,
                 __nv_bfloat16* __restrict__ dstB,
                 __nv_bfloat16* __restrict__ dstW)
{
    int e = blockIdx.x * 256 + threadIdx.x;
    const float* src; __nv_bfloat16* dst;
    if (e < NXQ)            { src = X;   dst = dstA; }
    else if (e < NXQ + NQQ) { src = Wq;  dst = dstB; e -= NXQ; }
    else if (e < NXQ + NQQ + NWQ) { src = Wpj; dst = dstW; e -= NXQ + NQQ; }
    else return;
    int r = e >> 8;
    int k = (e & 255) * 4;
    float4 v = *(const float4*)(src + (size_t)r * 1024 + k);
    uint32_t h0, l0, h1, l1;
    split2(v.x, v.y, h0, l0);
    split2(v.z, v.w, h1, l1);
    uint64_t hq = ((uint64_t)h1 << 32) | h0;
    uint64_t lq = ((uint64_t)l1 << 32) | l0;
    int mt = r >> 7, rr = r & 127, kt = k >> 5, kc = k & 31;
    char* d = (char*)dst + ((size_t)(mt * 32 + kt)) * 16384;
    *(uint64_t*)(d + swz(rr, kc >> 3) + (kc & 7) * 2)       = hq;
    *(uint64_t*)(d + swz(rr, (kc >> 3) + 4) + (kc & 7) * 2) = lq;
}

// ---------------------------------------------------------------------------
// bf16 split-2 tensor GEMM on pre-swizzled blocks. 128x128, BK=32,
// 3-stage bulk pipeline, mbarrier producer/consumer, 2 CTA/SM.
// NEW: B-fragment register double-buffer — LDSM for nb+1 issued before the
// MMAs of nb, hiding the ~29cyc LDSM->MMA latency under tensor work.
// ---------------------------------------------------------------------------
#define GST 32768
#define GEMM_SMEM (1024 + 3*GST)   // 99328

template<bool QKV, bool HAS_BIAS>
__global__ __launch_bounds__(256, 2)
void gemm_blk(const __nv_bfloat16* __restrict__ Ablk,
              const __nv_bfloat16* __restrict__ Bblk,
              const float* __restrict__ bias, float* __restrict__ Out,
              __nv_bfloat16* Qh, __nv_bfloat16* Ql,
              __nv_bfloat16* Kh, __nv_bfloat16* Kl,
              __nv_bfloat16* Vh, __nv_bfloat16* Vl, int N)
{
    extern __shared__ __align__(1024) char sm[];
    const uint32_t s0 = smem_u32(sm);
    const uint32_t e0 = s0 + 24;
    const uint32_t buf0 = s0 + 1024;
    const int tid = threadIdx.x, warp = tid >> 5, lane = tid & 31;
    const int wm = warp & 3, wn = warp >> 2;
    const int grp = lane >> 3, j = lane & 7;
    const int bm = blockIdx.y, bn = blockIdx.x;
    const int NKC = 32;

    if (tid == 0) {
        mbar_init(s0, 1); mbar_init(s0 + 8, 1); mbar_init(s0 + 16, 1);
        mbar_init(e0, 8); mbar_init(e0 + 8, 8); mbar_init(e0 + 16, 8);
    }
    __syncthreads();
    if (tid == 0) {
        #pragma unroll
        for (int p = 0; p < 2; p++) {
            uint32_t fb = s0 + p * 8;
            mbar_expect(fb, 2 * 16384);
            bulk_g2s(buf0 + p * GST,
                     (const char*)Ablk + ((size_t)bm * NKC + p) * 16384, 16384, fb);
            bulk_g2s(buf0 + p * GST + 16384,
                     (const char*)Bblk + ((size_t)bn * NKC + p) * 16384, 16384, fb);
        }
    }

    float c[2][8][4];
    #pragma unroll
    for (int a = 0; a < 2; a++)
        #pragma unroll
        for (int b = 0; b < 8; b++)
            #pragma unroll
            for (int q = 0; q < 4; q++) c[a][b][q] = 0.f;

    int stage = 0, ph = 0;
    for (int t = 0; t < NKC; t++) {
        if (tid == 0 && t + 2 < NKC) {
            int s2 = stage + 2; if (s2 >= 3) s2 -= 3;
            int f = (t + 2) / 3;
            if (f >= 1) mbar_wait(e0 + s2 * 8, (f - 1) & 1);
            uint32_t fb = s0 + s2 * 8;
            mbar_expect(fb, 2 * 16384);
            bulk_g2s(buf0 + s2 * GST,
                     (const char*)Ablk + ((size_t)bm * NKC + t + 2) * 16384,
                     16384, fb);
            bulk_g2s(buf0 + s2 * GST + 16384,
                     (const char*)Bblk + ((size_t)bn * NKC + t + 2) * 16384,
                     16384, fb);
        }
        mbar_wait(s0 + stage * 8, ph);
        uint32_t sA = buf0 + stage * GST;
        uint32_t sB = sA + 16384;

        #pragma unroll
        for (int ks = 0; ks < 2; ks++) {
            uint32_t ah[2][4], al[2][4];
            #pragma unroll
            for (int mt = 0; mt < 2; mt++) {
                int row = wm * 32 + mt * 16 + ((grp & 1) << 3) + j;
                int ch = ks * 2 + (grp >> 1);
                LDSM4(ah[mt][0], ah[mt][1], ah[mt][2], ah[mt][3], sA + swz(row, ch));
                LDSM4(al[mt][0], al[mt][1], al[mt][2], al[mt][3], sA + swz(row, ch + 4));
            }
            // B-fragment double buffer: bf[buf][0..3]=bh, [4..7]=bl
            uint32_t bf[2][8];
            {
                int rowb = wn * 64 + ((grp >> 1) << 3) + j;
                int chb = ks * 2 + (grp & 1);
                LDSM4(bf[0][0], bf[0][1], bf[0][2], bf[0][3], sB + swz(rowb, chb));
                LDSM4(bf[0][4], bf[0][5], bf[0][6], bf[0][7], sB + swz(rowb, chb + 4));
            }
            #pragma unroll
            for (int nb = 0; nb < 4; nb++) {
                const int cur = nb & 1, nxt = cur ^ 1;
                if (nb < 3) {
                    int rowb = wn * 64 + (nb + 1) * 16 + ((grp >> 1) << 3) + j;
                    int chb = ks * 2 + (grp & 1);
                    LDSM4(bf[nxt][0], bf[nxt][1], bf[nxt][2], bf[nxt][3],
                          sB + swz(rowb, chb));
                    LDSM4(bf[nxt][4], bf[nxt][5], bf[nxt][6], bf[nxt][7],
                          sB + swz(rowb, chb + 4));
                }
                #pragma unroll
                for (int mt = 0; mt < 2; mt++) {
                    MMA_BF16(c[mt][nb*2],   ah[mt], bf[cur][0], bf[cur][1]);
                    MMA_BF16(c[mt][nb*2+1], ah[mt], bf[cur][2], bf[cur][3]);
                }
                #pragma unroll
                for (int mt = 0; mt < 2; mt++) {
                    MMA_BF16(c[mt][nb*2],   ah[mt], bf[cur][4], bf[cur][5]);
                    MMA_BF16(c[mt][nb*2+1], ah[mt], bf[cur][6], bf[cur][7]);
                }
                #pragma unroll
                for (int mt = 0; mt < 2; mt++) {
                    MMA_BF16(c[mt][nb*2],   al[mt], bf[cur][0], bf[cur][1]);
                    MMA_BF16(c[mt][nb*2+1], al[mt], bf[cur][2], bf[cur][3]);
                }
            }
        }
        if (lane == 0) mbar_arrive(e0 + stage * 8);
        stage++; if (stage == 3) { stage = 0; ph ^= 1; }
    }

    // epilogue
    #pragma unroll
    for (int mt = 0; mt < 2; mt++) {
        int r0 = bm * 128 + wm * 32 + mt * 16 + (lane >> 2);
        #pragma unroll
        for (int ng = 0; ng < 8; ng++) {
            int col = bn * 128 + wn * 64 + ng * 8 + (lane & 3) * 2;
            if (!QKV) {
                float2 v0 = make_float2(c[mt][ng][0], c[mt][ng][1]);
                float2 v1 = make_float2(c[mt][ng][2], c[mt][ng][3]);
                if (HAS_BIAS) {
                    float2 bv = *(const float2*)&bias[col];
                    v0.x += bv.x; v0.y += bv.y;
                    v1.x += bv.x; v1.y += bv.y;
                }
                *(float2*)&Out[(size_t)r0 * N + col] = v0;
                *(float2*)&Out[(size_t)(r0 + 8) * N + col] = v1;
            } else {
                int h  = col / 192;
                int wc = col - h * 192;
                int ty = wc >> 6;
                int d  = wc & 63;
                __nv_bfloat16* Hp = (ty == 0) ? Qh : (ty == 1) ? Kh : Vh;
                __nv_bfloat16* Lp = (ty == 0) ? Ql : (ty == 1) ? Kl : Vl;
                float sc = (ty == 0) ? 0.125f : 1.0f;
                #pragma unroll
                for (int half = 0; half < 2; half++) {
                    int m = r0 + half * 8;
                    int b = m >> 11, tt = m & 2047;
                    int bh2 = b * Hh + h;
                    uint32_t hp, lp;
                    split2(c[mt][ng][half*2] * sc, c[mt][ng][half*2+1] * sc, hp, lp);
                    size_t base; uint32_t off;
                    if (ty == 0) {
                        base = ((size_t)bh2 * 16 + (tt >> 7)) * 16384;
                        off  = swz(tt & 127, d >> 3) + (d & 7) * 2;
                    } else {
                        base = ((size_t)bh2 * 32 + (tt >> 6)) * 8192;
                        off  = swz(tt & 63, d >> 3) + (d & 7) * 2;
                    }
                    *(uint32_t*)((char*)Hp + base + off) = hp;
                    *(uint32_t*)((char*)Lp + base + off) = lp;
                }
            }
        }
    }
}

// ---------------------------------------------------------------------------
// Tensor-core causal flash attention (R13/R15 validated, unchanged).
// ---------------------------------------------------------------------------
#define FA_SMEM (1024 + 32768 + 2*32768)
#define FSHIFT 16.0f

__global__ __launch_bounds__(256, 2)
void flash_attn_tc(const __nv_bfloat16* __restrict__ qh, const __nv_bfloat16* __restrict__ ql,
                   const __nv_bfloat16* __restrict__ kh, const __nv_bfloat16* __restrict__ kl,
                   const __nv_bfloat16* __restrict__ vh, const __nv_bfloat16* __restrict__ vl,
                   __nv_bfloat16* __restrict__ OA)
{
    extern __shared__ __align__(1024) char sm[];
    const uint32_t s0  = smem_u32(sm);
    const uint32_t QB = s0, FB0 = s0 + 8, FB1 = s0 + 16;
    const uint32_t EB0 = s0 + 24, EB1 = s0 + 32;
    const uint32_t sQh = s0 + 1024, sQl = sQh + 16384;
    const uint32_t kvb = s0 + 1024 + 32768;

    const int bh = blockIdx.x;
    const int qt = (gridDim.y - 1) - blockIdx.y;
    const int tid = threadIdx.x, w = tid >> 5, lane = tid & 31;
    const int g = lane >> 2, tg = lane & 3;
    const int grp = lane >> 3, j = lane & 7;
    const int nkt = 2 * qt + 2;

    if (tid == 0) {
        mbar_init(QB, 1); mbar_init(FB0, 1); mbar_init(FB1, 1);
        mbar_init(EB0, 8); mbar_init(EB1, 8);
    }
    __syncthreads();
    if (tid == 0) {
        mbar_expect(QB, 2 * 16384);
        bulk_g2s(sQh, (const char*)qh + ((size_t)bh * 16 + qt) * 16384, 16384, QB);
        bulk_g2s(sQl, (const char*)ql + ((size_t)bh * 16 + qt) * 16384, 16384, QB);
        #pragma unroll
        for (int p = 0; p < 2; p++) {
            uint32_t fb = p ? FB1 : FB0;
            uint32_t dst = kvb + p * 32768;
            size_t kb_ = ((size_t)bh * 32 + p) * 8192;
            mbar_expect(fb, 32768);
            bulk_g2s(dst,         (const char*)kh + kb_, 8192, fb);
            bulk_g2s(dst + 8192,  (const char*)kl + kb_, 8192, fb);
            bulk_g2s(dst + 16384, (const char*)vh + kb_, 8192, fb);
            bulk_g2s(dst + 24576, (const char*)vl + kb_, 8192, fb);
        }
    }
    mbar_wait(QB, 0);

    float o[8][4];
    #pragma unroll
    for (int nb = 0; nb < 8; nb++)
        #pragma unroll
        for (int e = 0; e < 4; e++) o[nb][e] = 0.f;
    float lA = 0.f, lB = 0.f;
    const int wrow0 = qt * 128 + w * 16;

    for (int kt = 0; kt < nkt; kt++) {
        mbar_wait((kt & 1) ? FB1 : FB0, (kt >> 1) & 1);
        uint32_t stg = kvb + (kt & 1) * 32768;
        uint32_t sKh = stg, sKl = stg + 8192;
        uint32_t sVh = stg + 16384, sVl = stg + 24576;

        if (kt * 64 <= wrow0 + 15) {
            float s[8][4];
            #pragma unroll
            for (int nb = 0; nb < 8; nb++)
                #pragma unroll
                for (int e = 0; e < 4; e++) s[nb][e] = 0.f;

            #pragma unroll
            for (int kb = 0; kb < 4; kb++) {
                int qrow = w * 16 + ((grp & 1) << 3) + j;
                uint32_t qoff = swz(qrow, kb * 2 + (grp >> 1));
                uint32_t qhf[4], qlf[4];
                LDSM4(qhf[0], qhf[1], qhf[2], qhf[3], sQh + qoff);
                LDSM4(qlf[0], qlf[1], qlf[2], qlf[3], sQl + qoff);
                #pragma unroll
                for (int p = 0; p < 4; p++) {
                    int rowb = p * 16 + ((grp >> 1) << 3) + j;
                    uint32_t off = swz(rowb, kb * 2 + (grp & 1));
                    uint32_t bhr[4], blr[4];
                    LDSM4(bhr[0], bhr[1], bhr[2], bhr[3], sKh + off);
                    LDSM4(blr[0], blr[1], blr[2], blr[3], sKl + off);
                    MMA_BF16(s[p*2],   qhf, bhr[0], bhr[1]);
                    MMA_BF16(s[p*2+1], qhf, bhr[2], bhr[3]);
                    MMA_BF16(s[p*2],   qhf, blr[0], blr[1]);
                    MMA_BF16(s[p*2+1], qhf, blr[2], blr[3]);
                    MMA_BF16(s[p*2],   qlf, bhr[0], bhr[1]);
                    MMA_BF16(s[p*2+1], qlf, bhr[2], bhr[3]);
                }
            }

            if (kt * 64 + 63 > wrow0) {
                int rowA = wrow0 + g, rowB = rowA + 8;
                #pragma unroll
                for (int nb = 0; nb < 8; nb++) {
                    int c0 = kt * 64 + nb * 8 + tg * 2;
                    if (c0 > rowA)     s[nb][0] = -INFINITY;
                    if (c0 + 1 > rowA) s[nb][1] = -INFINITY;
                    if (c0 > rowB)     s[nb][2] = -INFINITY;
                    if (c0 + 1 > rowB) s[nb][3] = -INFINITY;
                }
            }

            #pragma unroll
            for (int kb = 0; kb < 4; kb++) {
                float e00 = __expf(s[2*kb][0]   - FSHIFT);
                float e01 = __expf(s[2*kb][1]   - FSHIFT);
                float e02 = __expf(s[2*kb][2]   - FSHIFT);
                float e03 = __expf(s[2*kb][3]   - FSHIFT);
                float e10 = __expf(s[2*kb+1][0] - FSHIFT);
                float e11 = __expf(s[2*kb+1][1] - FSHIFT);
                float e12 = __expf(s[2*kb+1][2] - FSHIFT);
                float e13 = __expf(s[2*kb+1][3] - FSHIFT);
                lA += (e00 + e01) + (e10 + e11);
                lB += (e02 + e03) + (e12 + e13);
                uint32_t ph2[4], pl2[4];
                split2(e00, e01, ph2[0], pl2[0]);
                split2(e02, e03, ph2[1], pl2[1]);
                split2(e10, e11, ph2[2], pl2[2]);
                split2(e12, e13, ph2[3], pl2[3]);
                #pragma unroll
                for (int p = 0; p < 4; p++) {
                    int keyrow = kb * 16 + ((grp & 1) << 3) + j;
                    uint32_t off = swz(keyrow, p * 2 + (grp >> 1));
                    uint32_t vhr[4], vlr[4];
                    LDSM4T(vhr[0], vhr[1], vhr[2], vhr[3], sVh + off);
                    LDSM4T(vlr[0], vlr[1], vlr[2], vlr[3], sVl + off);
                    MMA_BF16(o[p*2],   ph2, vhr[0], vhr[1]);
                    MMA_BF16(o[p*2+1], ph2, vhr[2], vhr[3]);
                    MMA_BF16(o[p*2],   ph2, vlr[0], vlr[1]);
                    MMA_BF16(o[p*2+1], ph2, vlr[2], vlr[3]);
                    MMA_BF16(o[p*2],   pl2, vhr[0], vhr[1]);
                    MMA_BF16(o[p*2+1], pl2, vhr[2], vhr[3]);
                }
            }
        }
        if (lane == 0) mbar_arrive((kt & 1) ? EB1 : EB0);
        if (tid == 0 && kt + 2 < nkt) {
            mbar_wait((kt & 1) ? EB1 : EB0, (kt >> 1) & 1);
            uint32_t fb = (kt & 1) ? FB1 : FB0;
            uint32_t dst = kvb + (kt & 1) * 32768;
            size_t kb_ = ((size_t)bh * 32 + kt + 2) * 8192;
            mbar_expect(fb, 32768);
            bulk_g2s(dst,         (const char*)kh + kb_, 8192, fb);
            bulk_g2s(dst + 8192,  (const char*)kl + kb_, 8192, fb);
            bulk_g2s(dst + 16384, (const char*)vh + kb_, 8192, fb);
            bulk_g2s(dst + 24576, (const char*)vl + kb_, 8192, fb);
        }
    }

    #pragma unroll
    for (int d = 1; d < 4; d <<= 1) {
        lA += __shfl_xor_sync(0xffffffffu, lA, d);
        lB += __shfl_xor_sync(0xffffffffu, lB, d);
    }
    float invA = 1.f / lA, invB = 1.f / lB;
    int b = bh >> 4, h = bh & 15;
    #pragma unroll
    for (int nb = 0; nb < 8; nb++) {
        int col = h * 64 + nb * 8 + tg * 2;
        int ktc = col >> 5, kc = col & 31;
        #pragma unroll
        for (int half = 0; half < 2; half++) {
            int m = b * Tt + qt * 128 + w * 16 + g + half * 8;
            float inv = half ? invB : invA;
            uint32_t hp, lp;
            split2(o[nb][half*2] * inv, o[nb][half*2+1] * inv, hp, lp);
            char* d = (char*)OA + ((size_t)(m >> 7) * 32 + ktc) * 16384;
            *(uint32_t*)(d + swz(m & 127, kc >> 3) + (kc & 7) * 2)       = hp;
            *(uint32_t*)(d + swz(m & 127, (kc >> 3) + 4) + (kc & 7) * 2) = lp;
        }
    }
}

// ---------------------------------------------------------------------------
extern "C" void kernel_launch(void* const* d_in, const int* in_sizes, int n_in,
                              void* d_out, int out_size)
{
    const float* x     = (const float*)d_in[0];
    const float* Wqkv  = (const float*)d_in[1];
    const float* Wproj = (const float*)d_in[2];
    const float* bproj = (const float*)d_in[3];
    float* out = (float*)d_out;

    __nv_bfloat16 *Ab, *Bbk, *Wp, *qh, *ql, *kh, *kl, *vh, *vl;
    cudaGetSymbolAddress((void**)&Ab, g_Ablk);
    cudaGetSymbolAddress((void**)&Bbk, g_Bblk);
    cudaGetSymbolAddress((void**)&Wp, g_Wp);
    cudaGetSymbolAddress((void**)&qh, g_qh);
    cudaGetSymbolAddress((void**)&ql, g_ql);
    cudaGetSymbolAddress((void**)&kh, g_kh);
    cudaGetSymbolAddress((void**)&kl, g_kl);
    cudaGetSymbolAddress((void**)&vh, g_vh);
    cudaGetSymbolAddress((void**)&vl, g_vl);

    cudaFuncSetAttribute((const void*)gemm_blk<true, false>,
                         cudaFuncAttributeMaxDynamicSharedMemorySize, GEMM_SMEM);
    cudaFuncSetAttribute((const void*)gemm_blk<false, true>,
                         cudaFuncAttributeMaxDynamicSharedMemorySize, GEMM_SMEM);
    cudaFuncSetAttribute((const void*)flash_attn_tc,
                         cudaFuncAttributeMaxDynamicSharedMemorySize, FA_SMEM);

    // 1) fused block-convert (vectorized): x, Wqkv, Wproj
    int total = NXQ + NQQ + NWQ;
    convert_all<<<(total + 255) / 256, 256>>>(x, Wqkv, Wproj, Ab, Bbk, Wp);

    // 2) QKV projection -> q/k/v plane blocks
    gemm_blk<true, false><<<dim3(THREEC / 128, MROWS / 128), 256, GEMM_SMEM>>>(
        Ab, Bbk, nullptr, nullptr, qh, ql, kh, kl, vh, vl, THREEC);

    // 3) Causal flash attention -> proj-A blocks (overwrites Ab)
    flash_attn_tc<<<dim3(BH, Tt / 128), 256, FA_SMEM>>>(
        qh, ql, kh, kl, vh, vl, Ab);

    // 4) Output projection (+bias)
    gemm_blk<false, true><<<dim3(Cc / 128, MROWS / 128), 256, GEMM_SMEM>>>(
        Ab, Wp, bproj, out, nullptr, nullptr, nullptr, nullptr, nullptr,
        nullptr, Cc);
}

// round 17
// speedup vs baseline: 1.0087x; 1.0087x over previous
#include <cuda_runtime.h>
#include <cuda_bf16.h>
#include <math.h>
#include <stdint.h>

// Problem constants
#define Bb    4
#define Tt    2048
#define Cc    1024
#define Hh    16
#define HDd   64
#define MROWS (Bb*Tt)      // 8192
#define THREEC (3*Cc)      // 3072
#define BH    (Bb*Hh)      // 64

// Scratch: block-formatted operands. 16KB block = 128 rows x 128B;
// chunks 0-3 = hi plane (k 0..31), chunks 4-7 = lo plane.
__device__ __nv_bfloat16 g_Ablk[(size_t)MROWS * Cc * 2];    // 32MB
__device__ __nv_bfloat16 g_Bblk[(size_t)THREEC * Cc * 2];   // 12MB (Wqkv)
__device__ __nv_bfloat16 g_Wp[(size_t)Cc * Cc * 2];         // 4MB  (Wproj)
__device__ __nv_bfloat16 g_qh[(size_t)BH * Tt * HDd];
__device__ __nv_bfloat16 g_ql[(size_t)BH * Tt * HDd];
__device__ __nv_bfloat16 g_kh[(size_t)BH * Tt * HDd];
__device__ __nv_bfloat16 g_kl[(size_t)BH * Tt * HDd];
__device__ __nv_bfloat16 g_vh[(size_t)BH * Tt * HDd];
__device__ __nv_bfloat16 g_vl[(size_t)BH * Tt * HDd];

__device__ __forceinline__ uint32_t smem_u32(const void* p) {
    return (uint32_t)__cvta_generic_to_shared(p);
}
__device__ __forceinline__ void mbar_init(uint32_t a, uint32_t cnt) {
    asm volatile("mbarrier.init.shared.b64 [%0], %1;" :: "r"(a), "r"(cnt) : "memory");
}
__device__ __forceinline__ void mbar_expect(uint32_t a, uint32_t tx) {
    asm volatile("mbarrier.arrive.expect_tx.shared.b64 _, [%0], %1;"
                 :: "r"(a), "r"(tx) : "memory");
}
__device__ __forceinline__ void mbar_arrive(uint32_t a) {
    asm volatile("mbarrier.arrive.shared.b64 _, [%0];" :: "r"(a) : "memory");
}
__device__ __forceinline__ void mbar_wait(uint32_t a, uint32_t ph) {
    asm volatile(
        "{\n\t.reg .pred P;\n\t"
        "WL%=:\n\t"
        "mbarrier.try_wait.parity.shared::cta.b64 P, [%0], %1, 0x989680;\n\t"
        "@!P bra WL%=;\n\t}"
        :: "r"(a), "r"(ph) : "memory");
}
__device__ __forceinline__ void bulk_g2s(uint32_t dst, const void* src,
                                         uint32_t bytes, uint32_t mbar) {
    asm volatile(
        "cp.async.bulk.shared::cluster.global.mbarrier::complete_tx::bytes "
        "[%0], [%1], %2, [%3];"
        :: "r"(dst), "l"(src), "r"(bytes), "r"(mbar) : "memory");
}

#define LDSM4(r0, r1, r2, r3, a)                                              \
    asm volatile("ldmatrix.sync.aligned.m8n8.x4.shared.b16 {%0,%1,%2,%3}, [%4];" \
                 : "=r"(r0), "=r"(r1), "=r"(r2), "=r"(r3) : "r"(a))
#define LDSM4T(r0, r1, r2, r3, a)                                             \
    asm volatile("ldmatrix.sync.aligned.m8n8.x4.trans.shared.b16 {%0,%1,%2,%3}, [%4];" \
                 : "=r"(r0), "=r"(r1), "=r"(r2), "=r"(r3) : "r"(a))
#define MMA_BF16(c, a, b0, b1)                                                \
    asm volatile(                                                             \
        "mma.sync.aligned.m16n8k16.row.col.f32.bf16.bf16.f32 "                \
        "{%0,%1,%2,%3},{%4,%5,%6,%7},{%8,%9},{%0,%1,%2,%3};"                  \
        : "+f"((c)[0]), "+f"((c)[1]), "+f"((c)[2]), "+f"((c)[3])              \
        : "r"((a)[0]), "r"((a)[1]), "r"((a)[2]), "r"((a)[3]),                 \
          "r"(b0), "r"(b1))

__device__ __forceinline__ uint32_t swz(int row, int chunk) {
    return (uint32_t)(row * 128 + (((chunk) ^ (row & 7)) << 4));
}
__device__ __forceinline__ void split2(float a, float b, uint32_t& hi, uint32_t& lo) {
    __nv_bfloat16 ha = __float2bfloat16_rn(a);
    __nv_bfloat16 hb = __float2bfloat16_rn(b);
    __nv_bfloat16 la = __float2bfloat16_rn(a - __bfloat162float(ha));
    __nv_bfloat16 lb = __float2bfloat16_rn(b - __bfloat162float(hb));
    hi = ((uint32_t)__bfloat16_as_ushort(hb) << 16) | __bfloat16_as_ushort(ha);
    lo = ((uint32_t)__bfloat16_as_ushort(lb) << 16) | __bfloat16_as_ushort(la);
}

// ---------------------------------------------------------------------------
// Fused convert (vectorized): 4 floats/thread, one uint64 store per plane.
// x -> Ablk, Wqkv -> Bblk, Wproj -> Wp (all K=1024 rows; 256 quads/row).
// ---------------------------------------------------------------------------
#define NXQ  (MROWS * 256)
#define NQQ  (THREEC * 256)
#define NWQ  (Cc * 256)

__global__ __launch_bounds__(256)
void convert_all(const float* __restrict__ X, const float* __restrict__ Wq,
                 const float* __restrict__ Wpj,
                 __nv_bfloat16* __restrict__ dstA,
                 __nv_bfloat16* __restrict__ dstB,
                 __nv_bfloat16* __restrict__ dstW)
{
    int e = blockIdx.x * 256 + threadIdx.x;
    const float* src; __nv_bfloat16* dst;
    if (e < NXQ)            { src = X;   dst = dstA; }
    else if (e < NXQ + NQQ) { src = Wq;  dst = dstB; e -= NXQ; }
    else if (e < NXQ + NQQ + NWQ) { src = Wpj; dst = dstW; e -= NXQ + NQQ; }
    else return;
    int r = e >> 8;              // row
    int k = (e & 255) * 4;       // 4-aligned column
    float4 v = *(const float4*)(src + (size_t)r * 1024 + k);
    uint32_t h0, l0, h1, l1;
    split2(v.x, v.y, h0, l0);
    split2(v.z, v.w, h1, l1);
    uint64_t hq = ((uint64_t)h1 << 32) | h0;
    uint64_t lq = ((uint64_t)l1 << 32) | l0;
    int mt = r >> 7, rr = r & 127, kt = k >> 5, kc = k & 31;
    // kc is 4-aligned: both bf16 pairs land in one 16B chunk, bytes (kc&7)*2..+7
    char* d = (char*)dst + ((size_t)(mt * 32 + kt)) * 16384;
    *(uint64_t*)(d + swz(rr, kc >> 3) + (kc & 7) * 2)       = hq;
    *(uint64_t*)(d + swz(rr, (kc >> 3) + 4) + (kc & 7) * 2) = lq;
}

// ---------------------------------------------------------------------------
// bf16 split-2 tensor GEMM on pre-swizzled blocks (validated R11/R13/R15).
// 128x128, BK=32, 3-stage bulk pipeline, mbarrier producer/consumer, 2 CTA/SM.
// ---------------------------------------------------------------------------
#define GST 32768
#define GEMM_SMEM (1024 + 3*GST)   // 99328

template<bool QKV, bool HAS_BIAS>
__global__ __launch_bounds__(256, 2)
void gemm_blk(const __nv_bfloat16* __restrict__ Ablk,
              const __nv_bfloat16* __restrict__ Bblk,
              const float* __restrict__ bias, float* __restrict__ Out,
              __nv_bfloat16* Qh, __nv_bfloat16* Ql,
              __nv_bfloat16* Kh, __nv_bfloat16* Kl,
              __nv_bfloat16* Vh, __nv_bfloat16* Vl, int N)
{
    extern __shared__ __align__(1024) char sm[];
    const uint32_t s0 = smem_u32(sm);
    const uint32_t e0 = s0 + 24;
    const uint32_t buf0 = s0 + 1024;
    const int tid = threadIdx.x, warp = tid >> 5, lane = tid & 31;
    const int wm = warp & 3, wn = warp >> 2;
    const int grp = lane >> 3, j = lane & 7;
    const int bm = blockIdx.y, bn = blockIdx.x;
    const int NKC = 32;

    if (tid == 0) {
        mbar_init(s0, 1); mbar_init(s0 + 8, 1); mbar_init(s0 + 16, 1);
        mbar_init(e0, 8); mbar_init(e0 + 8, 8); mbar_init(e0 + 16, 8);
    }
    __syncthreads();
    if (tid == 0) {
        #pragma unroll
        for (int p = 0; p < 2; p++) {
            uint32_t fb = s0 + p * 8;
            mbar_expect(fb, 2 * 16384);
            bulk_g2s(buf0 + p * GST,
                     (const char*)Ablk + ((size_t)bm * NKC + p) * 16384, 16384, fb);
            bulk_g2s(buf0 + p * GST + 16384,
                     (const char*)Bblk + ((size_t)bn * NKC + p) * 16384, 16384, fb);
        }
    }

    float c[2][8][4];
    #pragma unroll
    for (int a = 0; a < 2; a++)
        #pragma unroll
        for (int b = 0; b < 8; b++)
            #pragma unroll
            for (int q = 0; q < 4; q++) c[a][b][q] = 0.f;

    int stage = 0, ph = 0;
    for (int t = 0; t < NKC; t++) {
        if (tid == 0 && t + 2 < NKC) {
            int s2 = stage + 2; if (s2 >= 3) s2 -= 3;
            int f = (t + 2) / 3;
            if (f >= 1) mbar_wait(e0 + s2 * 8, (f - 1) & 1);
            uint32_t fb = s0 + s2 * 8;
            mbar_expect(fb, 2 * 16384);
            bulk_g2s(buf0 + s2 * GST,
                     (const char*)Ablk + ((size_t)bm * NKC + t + 2) * 16384,
                     16384, fb);
            bulk_g2s(buf0 + s2 * GST + 16384,
                     (const char*)Bblk + ((size_t)bn * NKC + t + 2) * 16384,
                     16384, fb);
        }
        mbar_wait(s0 + stage * 8, ph);
        uint32_t sA = buf0 + stage * GST;
        uint32_t sB = sA + 16384;

        #pragma unroll
        for (int ks = 0; ks < 2; ks++) {
            uint32_t ah[2][4], al[2][4];
            #pragma unroll
            for (int mt = 0; mt < 2; mt++) {
                int row = wm * 32 + mt * 16 + ((grp & 1) << 3) + j;
                int ch = ks * 2 + (grp >> 1);
                LDSM4(ah[mt][0], ah[mt][1], ah[mt][2], ah[mt][3], sA + swz(row, ch));
                LDSM4(al[mt][0], al[mt][1], al[mt][2], al[mt][3], sA + swz(row, ch + 4));
            }
            #pragma unroll
            for (int nb = 0; nb < 4; nb++) {
                int rowb = wn * 64 + nb * 16 + ((grp >> 1) << 3) + j;
                int chb = ks * 2 + (grp & 1);
                uint32_t bh[4], bl[4];
                LDSM4(bh[0], bh[1], bh[2], bh[3], sB + swz(rowb, chb));
                LDSM4(bl[0], bl[1], bl[2], bl[3], sB + swz(rowb, chb + 4));
                #pragma unroll
                for (int mt = 0; mt < 2; mt++) {
                    MMA_BF16(c[mt][nb*2],   ah[mt], bh[0], bh[1]);
                    MMA_BF16(c[mt][nb*2+1], ah[mt], bh[2], bh[3]);
                }
                #pragma unroll
                for (int mt = 0; mt < 2; mt++) {
                    MMA_BF16(c[mt][nb*2],   ah[mt], bl[0], bl[1]);
                    MMA_BF16(c[mt][nb*2+1], ah[mt], bl[2], bl[3]);
                }
                #pragma unroll
                for (int mt = 0; mt < 2; mt++) {
                    MMA_BF16(c[mt][nb*2],   al[mt], bh[0], bh[1]);
                    MMA_BF16(c[mt][nb*2+1], al[mt], bh[2], bh[3]);
                }
            }
        }
        if (lane == 0) mbar_arrive(e0 + stage * 8);
        stage++; if (stage == 3) { stage = 0; ph ^= 1; }
    }

    // epilogue
    #pragma unroll
    for (int mt = 0; mt < 2; mt++) {
        int r0 = bm * 128 + wm * 32 + mt * 16 + (lane >> 2);
        #pragma unroll
        for (int ng = 0; ng < 8; ng++) {
            int col = bn * 128 + wn * 64 + ng * 8 + (lane & 3) * 2;
            if (!QKV) {
                float2 v0 = make_float2(c[mt][ng][0], c[mt][ng][1]);
                float2 v1 = make_float2(c[mt][ng][2], c[mt][ng][3]);
                if (HAS_BIAS) {
                    float2 bv = *(const float2*)&bias[col];
                    v0.x += bv.x; v0.y += bv.y;
                    v1.x += bv.x; v1.y += bv.y;
                }
                *(float2*)&Out[(size_t)r0 * N + col] = v0;
                *(float2*)&Out[(size_t)(r0 + 8) * N + col] = v1;
            } else {
                int h  = col / 192;
                int wc = col - h * 192;
                int ty = wc >> 6;
                int d  = wc & 63;
                __nv_bfloat16* Hp = (ty == 0) ? Qh : (ty == 1) ? Kh : Vh;
                __nv_bfloat16* Lp = (ty == 0) ? Ql : (ty == 1) ? Kl : Vl;
                float sc = (ty == 0) ? 0.125f : 1.0f;
                #pragma unroll
                for (int half = 0; half < 2; half++) {
                    int m = r0 + half * 8;
                    int b = m >> 11, tt = m & 2047;
                    int bh2 = b * Hh + h;
                    uint32_t hp, lp;
                    split2(c[mt][ng][half*2] * sc, c[mt][ng][half*2+1] * sc, hp, lp);
                    size_t base; uint32_t off;
                    if (ty == 0) {
                        base = ((size_t)bh2 * 16 + (tt >> 7)) * 16384;
                        off  = swz(tt & 127, d >> 3) + (d & 7) * 2;
                    } else {
                        base = ((size_t)bh2 * 32 + (tt >> 6)) * 8192;
                        off  = swz(tt & 63, d >> 3) + (d & 7) * 2;
                    }
                    *(uint32_t*)((char*)Hp + base + off) = hp;
                    *(uint32_t*)((char*)Lp + base + off) = lp;
                }
            }
        }
    }
}

// ---------------------------------------------------------------------------
// Tensor-core causal flash attention, fixed-shift softmax (M=16, math
// identical by shift invariance), deferred denominator reduction, exp
// interleaved with PV MMAs. mbarrier KV pipeline, 2 CTAs/SM. (R13/R15)
// ---------------------------------------------------------------------------
#define FA_SMEM (1024 + 32768 + 2*32768)
#define FSHIFT 16.0f

__global__ __launch_bounds__(256, 2)
void flash_attn_tc(const __nv_bfloat16* __restrict__ qh, const __nv_bfloat16* __restrict__ ql,
                   const __nv_bfloat16* __restrict__ kh, const __nv_bfloat16* __restrict__ kl,
                   const __nv_bfloat16* __restrict__ vh, const __nv_bfloat16* __restrict__ vl,
                   __nv_bfloat16* __restrict__ OA)
{
    extern __shared__ __align__(1024) char sm[];
    const uint32_t s0  = smem_u32(sm);
    const uint32_t QB = s0, FB0 = s0 + 8, FB1 = s0 + 16;
    const uint32_t EB0 = s0 + 24, EB1 = s0 + 32;
    const uint32_t sQh = s0 + 1024, sQl = sQh + 16384;
    const uint32_t kvb = s0 + 1024 + 32768;

    const int bh = blockIdx.x;
    const int qt = (gridDim.y - 1) - blockIdx.y;
    const int tid = threadIdx.x, w = tid >> 5, lane = tid & 31;
    const int g = lane >> 2, tg = lane & 3;
    const int grp = lane >> 3, j = lane & 7;
    const int nkt = 2 * qt + 2;

    if (tid == 0) {
        mbar_init(QB, 1); mbar_init(FB0, 1); mbar_init(FB1, 1);
        mbar_init(EB0, 8); mbar_init(EB1, 8);
    }
    __syncthreads();
    if (tid == 0) {
        mbar_expect(QB, 2 * 16384);
        bulk_g2s(sQh, (const char*)qh + ((size_t)bh * 16 + qt) * 16384, 16384, QB);
        bulk_g2s(sQl, (const char*)ql + ((size_t)bh * 16 + qt) * 16384, 16384, QB);
        #pragma unroll
        for (int p = 0; p < 2; p++) {
            uint32_t fb = p ? FB1 : FB0;
            uint32_t dst = kvb + p * 32768;
            size_t kb_ = ((size_t)bh * 32 + p) * 8192;
            mbar_expect(fb, 32768);
            bulk_g2s(dst,         (const char*)kh + kb_, 8192, fb);
            bulk_g2s(dst + 8192,  (const char*)kl + kb_, 8192, fb);
            bulk_g2s(dst + 16384, (const char*)vh + kb_, 8192, fb);
            bulk_g2s(dst + 24576, (const char*)vl + kb_, 8192, fb);
        }
    }
    mbar_wait(QB, 0);

    float o[8][4];
    #pragma unroll
    for (int nb = 0; nb < 8; nb++)
        #pragma unroll
        for (int e = 0; e < 4; e++) o[nb][e] = 0.f;
    float lA = 0.f, lB = 0.f;
    const int wrow0 = qt * 128 + w * 16;

    for (int kt = 0; kt < nkt; kt++) {
        mbar_wait((kt & 1) ? FB1 : FB0, (kt >> 1) & 1);
        uint32_t stg = kvb + (kt & 1) * 32768;
        uint32_t sKh = stg, sKl = stg + 8192;
        uint32_t sVh = stg + 16384, sVl = stg + 24576;

        if (kt * 64 <= wrow0 + 15) {
            float s[8][4];
            #pragma unroll
            for (int nb = 0; nb < 8; nb++)
                #pragma unroll
                for (int e = 0; e < 4; e++) s[nb][e] = 0.f;

            #pragma unroll
            for (int kb = 0; kb < 4; kb++) {
                int qrow = w * 16 + ((grp & 1) << 3) + j;
                uint32_t qoff = swz(qrow, kb * 2 + (grp >> 1));
                uint32_t qhf[4], qlf[4];
                LDSM4(qhf[0], qhf[1], qhf[2], qhf[3], sQh + qoff);
                LDSM4(qlf[0], qlf[1], qlf[2], qlf[3], sQl + qoff);
                #pragma unroll
                for (int p = 0; p < 4; p++) {
                    int rowb = p * 16 + ((grp >> 1) << 3) + j;
                    uint32_t off = swz(rowb, kb * 2 + (grp & 1));
                    uint32_t bhr[4], blr[4];
                    LDSM4(bhr[0], bhr[1], bhr[2], bhr[3], sKh + off);
                    LDSM4(blr[0], blr[1], blr[2], blr[3], sKl + off);
                    MMA_BF16(s[p*2],   qhf, bhr[0], bhr[1]);
                    MMA_BF16(s[p*2+1], qhf, bhr[2], bhr[3]);
                    MMA_BF16(s[p*2],   qhf, blr[0], blr[1]);
                    MMA_BF16(s[p*2+1], qhf, blr[2], blr[3]);
                    MMA_BF16(s[p*2],   qlf, bhr[0], bhr[1]);
                    MMA_BF16(s[p*2+1], qlf, bhr[2], bhr[3]);
                }
            }

            if (kt * 64 + 63 > wrow0) {
                int rowA = wrow0 + g, rowB = rowA + 8;
                #pragma unroll
                for (int nb = 0; nb < 8; nb++) {
                    int c0 = kt * 64 + nb * 8 + tg * 2;
                    if (c0 > rowA)     s[nb][0] = -INFINITY;
                    if (c0 + 1 > rowA) s[nb][1] = -INFINITY;
                    if (c0 > rowB)     s[nb][2] = -INFINITY;
                    if (c0 + 1 > rowB) s[nb][3] = -INFINITY;
                }
            }

            #pragma unroll
            for (int kb = 0; kb < 4; kb++) {
                float e00 = __expf(s[2*kb][0]   - FSHIFT);
                float e01 = __expf(s[2*kb][1]   - FSHIFT);
                float e02 = __expf(s[2*kb][2]   - FSHIFT);
                float e03 = __expf(s[2*kb][3]   - FSHIFT);
                float e10 = __expf(s[2*kb+1][0] - FSHIFT);
                float e11 = __expf(s[2*kb+1][1] - FSHIFT);
                float e12 = __expf(s[2*kb+1][2] - FSHIFT);
                float e13 = __expf(s[2*kb+1][3] - FSHIFT);
                lA += (e00 + e01) + (e10 + e11);
                lB += (e02 + e03) + (e12 + e13);
                uint32_t ph2[4], pl2[4];
                split2(e00, e01, ph2[0], pl2[0]);
                split2(e02, e03, ph2[1], pl2[1]);
                split2(e10, e11, ph2[2], pl2[2]);
                split2(e12, e13, ph2[3], pl2[3]);
                #pragma unroll
                for (int p = 0; p < 4; p++) {
                    int keyrow = kb * 16 + ((grp & 1) << 3) + j;
                    uint32_t off = swz(keyrow, p * 2 + (grp >> 1));
                    uint32_t vhr[4], vlr[4];
                    LDSM4T(vhr[0], vhr[1], vhr[2], vhr[3], sVh + off);
                    LDSM4T(vlr[0], vlr[1], vlr[2], vlr[3], sVl + off);
                    MMA_BF16(o[p*2],   ph2, vhr[0], vhr[1]);
                    MMA_BF16(o[p*2+1], ph2, vhr[2], vhr[3]);
                    MMA_BF16(o[p*2],   ph2, vlr[0], vlr[1]);
                    MMA_BF16(o[p*2+1], ph2, vlr[2], vlr[3]);
                    MMA_BF16(o[p*2],   pl2, vhr[0], vhr[1]);
                    MMA_BF16(o[p*2+1], pl2, vhr[2], vhr[3]);
                }
            }
        }
        if (lane == 0) mbar_arrive((kt & 1) ? EB1 : EB0);
        if (tid == 0 && kt + 2 < nkt) {
            mbar_wait((kt & 1) ? EB1 : EB0, (kt >> 1) & 1);
            uint32_t fb = (kt & 1) ? FB1 : FB0;
            uint32_t dst = kvb + (kt & 1) * 32768;
            size_t kb_ = ((size_t)bh * 32 + kt + 2) * 8192;
            mbar_expect(fb, 32768);
            bulk_g2s(dst,         (const char*)kh + kb_, 8192, fb);
            bulk_g2s(dst + 8192,  (const char*)kl + kb_, 8192, fb);
            bulk_g2s(dst + 16384, (const char*)vh + kb_, 8192, fb);
            bulk_g2s(dst + 24576, (const char*)vl + kb_, 8192, fb);
        }
    }

    #pragma unroll
    for (int d = 1; d < 4; d <<= 1) {
        lA += __shfl_xor_sync(0xffffffffu, lA, d);
        lB += __shfl_xor_sync(0xffffffffu, lB, d);
    }
    float invA = 1.f / lA, invB = 1.f / lB;
    int b = bh >> 4, h = bh & 15;
    #pragma unroll
    for (int nb = 0; nb < 8; nb++) {
        int col = h * 64 + nb * 8 + tg * 2;
        int ktc = col >> 5, kc = col & 31;
        #pragma unroll
        for (int half = 0; half < 2; half++) {
            int m = b * Tt + qt * 128 + w * 16 + g + half * 8;
            float inv = half ? invB : invA;
            uint32_t hp, lp;
            split2(o[nb][half*2] * inv, o[nb][half*2+1] * inv, hp, lp);
            char* d = (char*)OA + ((size_t)(m >> 7) * 32 + ktc) * 16384;
            *(uint32_t*)(d + swz(m & 127, kc >> 3) + (kc & 7) * 2)       = hp;
            *(uint32_t*)(d + swz(m & 127, (kc >> 3) + 4) + (kc & 7) * 2) = lp;
        }
    }
}

// ---------------------------------------------------------------------------
extern "C" void kernel_launch(void* const* d_in, const int* in_sizes, int n_in,
                              void* d_out, int out_size)
{
    const float* x     = (const float*)d_in[0];
    const float* Wqkv  = (const float*)d_in[1];
    const float* Wproj = (const float*)d_in[2];
    const float* bproj = (const float*)d_in[3];
    float* out = (float*)d_out;

    __nv_bfloat16 *Ab, *Bbk, *Wp, *qh, *ql, *kh, *kl, *vh, *vl;
    cudaGetSymbolAddress((void**)&Ab, g_Ablk);
    cudaGetSymbolAddress((void**)&Bbk, g_Bblk);
    cudaGetSymbolAddress((void**)&Wp, g_Wp);
    cudaGetSymbolAddress((void**)&qh, g_qh);
    cudaGetSymbolAddress((void**)&ql, g_ql);
    cudaGetSymbolAddress((void**)&kh, g_kh);
    cudaGetSymbolAddress((void**)&kl, g_kl);
    cudaGetSymbolAddress((void**)&vh, g_vh);
    cudaGetSymbolAddress((void**)&vl, g_vl);

    cudaFuncSetAttribute((const void*)gemm_blk<true, false>,
                         cudaFuncAttributeMaxDynamicSharedMemorySize, GEMM_SMEM);
    cudaFuncSetAttribute((const void*)gemm_blk<false, true>,
                         cudaFuncAttributeMaxDynamicSharedMemorySize, GEMM_SMEM);
    cudaFuncSetAttribute((const void*)flash_attn_tc,
                         cudaFuncAttributeMaxDynamicSharedMemorySize, FA_SMEM);

    // 1) fused block-convert (vectorized): x, Wqkv, Wproj
    int total = NXQ + NQQ + NWQ;
    convert_all<<<(total + 255) / 256, 256>>>(x, Wqkv, Wproj, Ab, Bbk, Wp);

    // 2) QKV projection -> q/k/v plane blocks
    gemm_blk<true, false><<<dim3(THREEC / 128, MROWS / 128), 256, GEMM_SMEM>>>(
        Ab, Bbk, nullptr, nullptr, qh, ql, kh, kl, vh, vl, THREEC);

    // 3) Causal flash attention -> proj-A blocks (overwrites Ab)
    flash_attn_tc<<<dim3(BH, Tt / 128), 256, FA_SMEM>>>(
        qh, ql, kh, kl, vh, vl, Ab);

    // 4) Output projection (+bias)
    gemm_blk<false, true><<<dim3(Cc / 128, MROWS / 128), 256, GEMM_SMEM>>>(
        Ab, Wp, bproj, out, nullptr, nullptr, nullptr, nullptr, nullptr,
        nullptr, Cc);
}